// round 2
// baseline (speedup 1.0000x reference)
#include <cuda_runtime.h>
#include <cuda_bf16.h>

#define BB 8
#define NN 2048
#define FF 256
#define ALPHA 0.2f

// -------- scratch (device globals; no allocation allowed) --------
__device__ float g_Wh[BB * NN * FF];     // 16 MB
__device__ float g_s1[BB * NN];
__device__ float g_s2[BB * NN];
__device__ float g_s2max[BB];

// ============================================================
// Kernel 1: Wh = h @ W   (M=16384, K=256, Ncols=256)
// CTA tile 64x64, 256 threads, thread tile 4x4, K-step 16
// ============================================================
__global__ __launch_bounds__(256) void gemm_wh_kernel(
    const float* __restrict__ h, const float* __restrict__ W)
{
    __shared__ float As[16][68];   // [k][m], stride 68 floats = 272B (16B multiple)
    __shared__ float Bs[16][68];   // [k][n]

    const int tid = threadIdx.x;
    const int tx = tid & 15;       // n-group
    const int ty = tid >> 4;       // m-group
    const int m0 = blockIdx.x * 64;
    const int n0 = blockIdx.y * 64;

    const int la_m  = tid >> 2;         // 0..63
    const int la_k4 = (tid & 3) * 4;    // 0,4,8,12
    const int lb_k  = tid >> 4;         // 0..15
    const int lb_n4 = (tid & 15) * 4;   // 0..60

    float acc[4][4];
#pragma unroll
    for (int i = 0; i < 4; i++)
#pragma unroll
        for (int j = 0; j < 4; j++) acc[i][j] = 0.f;

    for (int k0 = 0; k0 < FF; k0 += 16) {
        float4 av = *(const float4*)&h[(size_t)(m0 + la_m) * FF + k0 + la_k4];
        float4 bv = *(const float4*)&W[(size_t)(k0 + lb_k) * FF + n0 + lb_n4];
        As[la_k4 + 0][la_m] = av.x;
        As[la_k4 + 1][la_m] = av.y;
        As[la_k4 + 2][la_m] = av.z;
        As[la_k4 + 3][la_m] = av.w;
        *(float4*)&Bs[lb_k][lb_n4] = bv;
        __syncthreads();
#pragma unroll
        for (int k = 0; k < 16; k++) {
            float4 a4 = *(const float4*)&As[k][ty * 4];
            float4 b4 = *(const float4*)&Bs[k][tx * 4];
            float a[4] = {a4.x, a4.y, a4.z, a4.w};
            float b[4] = {b4.x, b4.y, b4.z, b4.w};
#pragma unroll
            for (int i = 0; i < 4; i++)
#pragma unroll
                for (int j = 0; j < 4; j++) acc[i][j] += a[i] * b[j];
        }
        __syncthreads();
    }
#pragma unroll
    for (int i = 0; i < 4; i++) {
        float4 v = make_float4(acc[i][0], acc[i][1], acc[i][2], acc[i][3]);
        *(float4*)&g_Wh[(size_t)(m0 + ty * 4 + i) * FF + n0 + tx * 4] = v;
    }
}

// ============================================================
// Kernel 2: s1[r] = Wh[r,:]·a1 ; s2[r] = Wh[r,:]·a2
// one warp per row, 8 warps per block
// ============================================================
__global__ __launch_bounds__(256) void s1s2_kernel(const float* __restrict__ a)
{
    const int warp = threadIdx.x >> 5;
    const int lane = threadIdx.x & 31;
    const int row = blockIdx.x * 8 + warp;   // 0..16383
    const float* wh = g_Wh + (size_t)row * FF;
    float s1 = 0.f, s2 = 0.f;
#pragma unroll
    for (int k = 0; k < 8; k++) {
        float w = wh[k * 32 + lane];
        s1 += w * a[k * 32 + lane];
        s2 += w * a[FF + k * 32 + lane];
    }
#pragma unroll
    for (int o = 16; o; o >>= 1) {
        s1 += __shfl_xor_sync(0xffffffffu, s1, o);
        s2 += __shfl_xor_sync(0xffffffffu, s2, o);
    }
    if (lane == 0) { g_s1[row] = s1; g_s2[row] = s2; }
}

// ============================================================
// Kernel 3: per-batch max of s2 (softmax upper-bound stabilizer)
// ============================================================
__global__ __launch_bounds__(256) void s2max_kernel()
{
    __shared__ float red[256];
    const int b = blockIdx.x;
    float m = -1e30f;
    for (int i = threadIdx.x; i < NN; i += 256) m = fmaxf(m, g_s2[b * NN + i]);
    red[threadIdx.x] = m;
    __syncthreads();
#pragma unroll
    for (int s = 128; s; s >>= 1) {
        if (threadIdx.x < s) red[threadIdx.x] = fmaxf(red[threadIdx.x], red[threadIdx.x + s]);
        __syncthreads();
    }
    if (threadIdx.x == 0) g_s2max[b] = red[0];
}

// ============================================================
// Kernel 4: fused masked softmax + PV
// CTA: 64 queries x 256 features, BJ=32 j-tile, 256 threads
// thread tile: 4 queries x 16 features (64 accumulators)
// m_i = lrelu(s1_i + max_j s2_j) >= true rowmax  -> no rescaling needed
// ============================================================
#define TI 64
#define BJ 32

__global__ __launch_bounds__(256, 2) void attn_kernel(
    const int* __restrict__ adj, float* __restrict__ out)
{
    __shared__ float Vs[BJ][FF];    // 32 KB
    __shared__ float Ps[BJ][TI];    // 8 KB (layout [j][i] for float4 reads)
    __shared__ float Zs[TI];

    const int tid = threadIdx.x;
    const int b  = blockIdx.y;
    const int i0 = blockIdx.x * TI;

    // P-compute mapping: each thread owns (one query row, 8 j's)
    const int pi  = tid >> 2;           // 0..63
    const int pj0 = (tid & 3) * 8;      // 0,8,16,24

    const float s1v = g_s1[b * NN + i0 + pi];
    const float ms2 = g_s2max[b];
    const float tpre = s1v + ms2;
    const float mi = tpre > 0.f ? tpre : ALPHA * tpre;
    float zloc = 0.f;

    // FMA mapping
    const int tx = tid & 15;   // feature group: cols tx*16..tx*16+15
    const int ty = tid >> 4;   // query group: rows ty*4..ty*4+3

    float acc[4][16];
#pragma unroll
    for (int q = 0; q < 4; q++)
#pragma unroll
        for (int f = 0; f < 16; f++) acc[q][f] = 0.f;

    const float* __restrict__ WhB = g_Wh + (size_t)b * NN * FF;
    const int*   __restrict__ adjRow = adj + (size_t)b * NN * NN + (size_t)(i0 + pi) * NN;
    const float* __restrict__ s2B = g_s2 + b * NN;

    for (int j0 = 0; j0 < NN; j0 += BJ) {
        // ---- stage V tile (global/L2 -> smem), 8 float4 per thread ----
#pragma unroll
        for (int r = 0; r < 8; r++) {
            int idx = tid + r * 256;          // float4 index 0..2047
            int vj = idx >> 6;                // 0..31
            int vf = (idx & 63) << 2;         // 0..252
            *(float4*)&Vs[vj][vf] = *(const float4*)&WhB[(size_t)(j0 + vj) * FF + vf];
        }
        // ---- compute P tile: p = adj ? exp(lrelu(s1+s2) - mi) : 0 ----
        int4 a0 = *(const int4*)&adjRow[j0 + pj0];
        int4 a1 = *(const int4*)&adjRow[j0 + pj0 + 4];
        int am[8] = {a0.x, a0.y, a0.z, a0.w, a1.x, a1.y, a1.z, a1.w};
#pragma unroll
        for (int k = 0; k < 8; k++) {
            float e = s1v + s2B[j0 + pj0 + k];
            e = e > 0.f ? e : ALPHA * e;
            float p = (am[k] > 0) ? __expf(e - mi) : 0.f;
            Ps[pj0 + k][pi] = p;
            zloc += p;
        }
        __syncthreads();
        // ---- FMA: acc[q][f] += P[k][q] * V[k][f] ----
#pragma unroll 8
        for (int k = 0; k < BJ; k++) {
            float4 pv = *(const float4*)&Ps[k][ty * 4];
            float p[4] = {pv.x, pv.y, pv.z, pv.w};
            float4 v0 = *(const float4*)&Vs[k][tx * 16 + 0];
            float4 v1 = *(const float4*)&Vs[k][tx * 16 + 4];
            float4 v2 = *(const float4*)&Vs[k][tx * 16 + 8];
            float4 v3 = *(const float4*)&Vs[k][tx * 16 + 12];
            float v[16] = {v0.x, v0.y, v0.z, v0.w, v1.x, v1.y, v1.z, v1.w,
                           v2.x, v2.y, v2.z, v2.w, v3.x, v3.y, v3.z, v3.w};
#pragma unroll
            for (int q = 0; q < 4; q++)
#pragma unroll
                for (int f = 0; f < 16; f++) acc[q][f] += p[q] * v[f];
        }
        __syncthreads();
    }

    // ---- Z reduction: 4 consecutive lanes share a query row ----
    zloc += __shfl_xor_sync(0xffffffffu, zloc, 1);
    zloc += __shfl_xor_sync(0xffffffffu, zloc, 2);
    if ((tid & 3) == 0) Zs[pi] = zloc;
    __syncthreads();

    // ---- epilogue: out = acc / Z ----
#pragma unroll
    for (int q = 0; q < 4; q++) {
        float rz = 1.f / Zs[ty * 4 + q];
        size_t base = ((size_t)b * NN + (i0 + ty * 4 + q)) * FF + tx * 16;
#pragma unroll
        for (int l = 0; l < 4; l++) {
            float4 v = make_float4(acc[q][l * 4 + 0] * rz, acc[q][l * 4 + 1] * rz,
                                   acc[q][l * 4 + 2] * rz, acc[q][l * 4 + 3] * rz);
            *(float4*)&out[base + l * 4] = v;
        }
    }
}

// ============================================================
// launch
// ============================================================
extern "C" void kernel_launch(void* const* d_in, const int* in_sizes, int n_in,
                              void* d_out, int out_size)
{
    const float* h   = (const float*)d_in[0];
    const int*   adj = (const int*)d_in[1];
    const float* W   = (const float*)d_in[2];
    const float* a   = (const float*)d_in[3];
    float* out = (float*)d_out;

    // Wh GEMM: grid (16384/64, 256/64)
    dim3 g1(BB * NN / 64, FF / 64);
    gemm_wh_kernel<<<g1, 256>>>(h, W);

    // s1/s2: one warp per row
    s1s2_kernel<<<BB * NN / 8, 256>>>(a);

    // per-batch s2 max
    s2max_kernel<<<BB, 256>>>();

    // fused masked softmax + PV
    dim3 g4(NN / TI, BB);
    attn_kernel<<<g4, 256>>>(adj, out);
}

// round 4
// speedup vs baseline: 3.2480x; 3.2480x over previous
#include <cuda_runtime.h>
#include <cuda_bf16.h>
#include <cstdint>

#define BB 8
#define NN 2048
#define FF 256
#define ALPHA 0.2f

// -------- scratch (device globals; no allocation allowed) --------
__device__ float g_Wh[BB * NN * FF];                 // 16 MB
__device__ __nv_bfloat16 g_WhT_hi[BB * FF * NN];     // 8 MB  (Wh^T, bf16 high part)
__device__ __nv_bfloat16 g_WhT_lo[BB * FF * NN];     // 8 MB  (Wh^T, bf16 low part)
__device__ float g_s1[BB * NN];
__device__ float g_s2[BB * NN];
__device__ float g_s2max[BB];

// ============================================================
// Kernel 1: Wh = h @ W   (fp32 CUDA-core)
// ============================================================
__global__ __launch_bounds__(256) void gemm_wh_kernel(
    const float* __restrict__ h, const float* __restrict__ W)
{
    __shared__ float As[16][68];
    __shared__ float Bs[16][68];

    const int tid = threadIdx.x;
    const int tx = tid & 15;
    const int ty = tid >> 4;
    const int m0 = blockIdx.x * 64;
    const int n0 = blockIdx.y * 64;

    const int la_m  = tid >> 2;
    const int la_k4 = (tid & 3) * 4;
    const int lb_k  = tid >> 4;
    const int lb_n4 = (tid & 15) * 4;

    float acc[4][4];
#pragma unroll
    for (int i = 0; i < 4; i++)
#pragma unroll
        for (int j = 0; j < 4; j++) acc[i][j] = 0.f;

    for (int k0 = 0; k0 < FF; k0 += 16) {
        float4 av = *(const float4*)&h[(size_t)(m0 + la_m) * FF + k0 + la_k4];
        float4 bv = *(const float4*)&W[(size_t)(k0 + lb_k) * FF + n0 + lb_n4];
        As[la_k4 + 0][la_m] = av.x;
        As[la_k4 + 1][la_m] = av.y;
        As[la_k4 + 2][la_m] = av.z;
        As[la_k4 + 3][la_m] = av.w;
        *(float4*)&Bs[lb_k][lb_n4] = bv;
        __syncthreads();
#pragma unroll
        for (int k = 0; k < 16; k++) {
            float4 a4 = *(const float4*)&As[k][ty * 4];
            float4 b4 = *(const float4*)&Bs[k][tx * 4];
            float a[4] = {a4.x, a4.y, a4.z, a4.w};
            float b[4] = {b4.x, b4.y, b4.z, b4.w};
#pragma unroll
            for (int i = 0; i < 4; i++)
#pragma unroll
                for (int j = 0; j < 4; j++) acc[i][j] += a[i] * b[j];
        }
        __syncthreads();
    }
#pragma unroll
    for (int i = 0; i < 4; i++) {
        float4 v = make_float4(acc[i][0], acc[i][1], acc[i][2], acc[i][3]);
        *(float4*)&g_Wh[(size_t)(m0 + ty * 4 + i) * FF + n0 + tx * 4] = v;
    }
}

// ============================================================
// Kernel 2: s1/s2 row dots
// ============================================================
__global__ __launch_bounds__(256) void s1s2_kernel(const float* __restrict__ a)
{
    const int warp = threadIdx.x >> 5;
    const int lane = threadIdx.x & 31;
    const int row = blockIdx.x * 8 + warp;
    const float* wh = g_Wh + (size_t)row * FF;
    float s1 = 0.f, s2 = 0.f;
#pragma unroll
    for (int k = 0; k < 8; k++) {
        float w = wh[k * 32 + lane];
        s1 += w * a[k * 32 + lane];
        s2 += w * a[FF + k * 32 + lane];
    }
#pragma unroll
    for (int o = 16; o; o >>= 1) {
        s1 += __shfl_xor_sync(0xffffffffu, s1, o);
        s2 += __shfl_xor_sync(0xffffffffu, s2, o);
    }
    if (lane == 0) { g_s1[row] = s1; g_s2[row] = s2; }
}

// ============================================================
// Kernel 3: per-batch max of s2
// ============================================================
__global__ __launch_bounds__(256) void s2max_kernel()
{
    __shared__ float red[256];
    const int b = blockIdx.x;
    float m = -1e30f;
    for (int i = threadIdx.x; i < NN; i += 256) m = fmaxf(m, g_s2[b * NN + i]);
    red[threadIdx.x] = m;
    __syncthreads();
#pragma unroll
    for (int s = 128; s; s >>= 1) {
        if (threadIdx.x < s) red[threadIdx.x] = fmaxf(red[threadIdx.x], red[threadIdx.x + s]);
        __syncthreads();
    }
    if (threadIdx.x == 0) g_s2max[b] = red[0];
}

// ============================================================
// Kernel 3b: Wh -> Wh^T split to bf16 hi/lo  (per batch transpose)
// ============================================================
__global__ __launch_bounds__(256) void split_transpose_kernel()
{
    __shared__ float t[32][33];
    const int b = blockIdx.z;
    const int n0 = blockIdx.x * 32, f0 = blockIdx.y * 32;
    const int x = threadIdx.x & 31, y = threadIdx.x >> 5;   // y 0..7
    const float* src = g_Wh + ((size_t)b * NN + n0) * FF + f0;
#pragma unroll
    for (int r = 0; r < 4; r++)
        t[y * 4 + r][x] = src[(size_t)(y * 4 + r) * FF + x];
    __syncthreads();
#pragma unroll
    for (int r = 0; r < 4; r++) {
        const int f = y * 4 + r;
        float v = t[x][f];
        __nv_bfloat16 hi = __float2bfloat16_rn(v);
        float rem = v - __bfloat162float(hi);
        size_t o = ((size_t)b * FF + f0 + f) * NN + n0 + x;
        g_WhT_hi[o] = hi;
        g_WhT_lo[o] = __float2bfloat16_rn(rem);
    }
}

// ============================================================
// Kernel 4: fused masked softmax + PV via mma.sync (split-bf16)
// CTA: 64 queries x 256 features, 8 warps (2m x 4n), warp 32q x 64f
// K-tile KJ=64 over j. Row stride 144B => conflict-free frag LDS.
// ============================================================
#define TI 64
#define KJ 64
#define VST 144          // bytes per smem row (64 bf16 data + pad)

#define SM_VH 0
#define SM_VL (SM_VH + FF * VST)            // 36864
#define SM_PH (SM_VL + FF * VST)            // 73728
#define SM_PL (SM_PH + TI * VST)            // 82944
#define SM_ZS (SM_PL + TI * VST)            // 92160
#define SM_TOTAL (SM_ZS + TI * 4)           // 92416

__device__ __forceinline__ void mma16816(float* c, const uint32_t* a, const uint32_t* b)
{
    asm volatile(
        "mma.sync.aligned.m16n8k16.row.col.f32.bf16.bf16.f32 "
        "{%0,%1,%2,%3}, {%4,%5,%6,%7}, {%8,%9}, {%0,%1,%2,%3};"
        : "+f"(c[0]), "+f"(c[1]), "+f"(c[2]), "+f"(c[3])
        : "r"(a[0]), "r"(a[1]), "r"(a[2]), "r"(a[3]), "r"(b[0]), "r"(b[1]));
}

__global__ __launch_bounds__(256) void attn_mma_kernel(
    const int* __restrict__ adj, float* __restrict__ out)
{
    extern __shared__ char smem[];
    const int tid = threadIdx.x;
    const int wid = tid >> 5;
    const int lane = tid & 31;
    const int b = blockIdx.y;
    const int i0 = blockIdx.x * TI;

    // warp tile: rows m0w..m0w+31, cols n0w..n0w+63
    const int m0w = (wid & 1) * 32;
    const int n0w = (wid >> 1) * 64;

    // P-compute mapping: thread -> (row r, 16 j's starting at jbase)
    const int r = tid >> 2;
    const int jbase = (tid & 3) * 16;

    const float s1v = g_s1[b * NN + i0 + r];
    const float ms2 = g_s2max[b];
    const float tpre = s1v + ms2;
    const float mi = tpre > 0.f ? tpre : ALPHA * tpre;
    float zloc = 0.f;

    const int* __restrict__ adjR = adj + ((size_t)b * NN + i0 + r) * NN;
    const float* __restrict__ s2B = g_s2 + b * NN;
    const uint4* __restrict__ whtHi = (const uint4*)(g_WhT_hi + (size_t)b * FF * NN);
    const uint4* __restrict__ whtLo = (const uint4*)(g_WhT_lo + (size_t)b * FF * NN);

    float acc[2][8][4];
#pragma unroll
    for (int mt = 0; mt < 2; mt++)
#pragma unroll
        for (int nt = 0; nt < 8; nt++)
#pragma unroll
            for (int q = 0; q < 4; q++) acc[mt][nt][q] = 0.f;

    const int ldq = lane >> 2;          // 0..7 (frag row group)
    const int ldr = (lane & 3) * 4;     // byte offset for k pair

    for (int jt = 0; jt < NN / KJ; jt++) {
        const int j0 = jt * KJ;

        // ---- stage V^T hi/lo tiles: 256 f-rows x 64 j bf16 ----
#pragma unroll
        for (int it = 0; it < 8; it++) {
            const int idx = tid + it * 256;
            const int f = idx >> 3;
            const int c = idx & 7;
            const int gi = f * (NN / 8) + (j0 >> 3) + c;
            const uint32_t so = f * VST + c * 16;
            *(uint4*)(smem + SM_VH + so) = whtHi[gi];
            *(uint4*)(smem + SM_VL + so) = whtLo[gi];
        }

        // ---- compute P tile [64 x 64], split to bf16 hi/lo ----
#pragma unroll
        for (int g = 0; g < 4; g++) {
            const int j = j0 + jbase + g * 4;
            int4 am = *(const int4*)&adjR[j];
            float4 s2q = *(const float4*)&s2B[j];
            float p0, p1, p2, p3, ev;
            ev = s1v + s2q.x; ev = ev > 0.f ? ev : ALPHA * ev;
            p0 = (am.x > 0) ? __expf(ev - mi) : 0.f;
            ev = s1v + s2q.y; ev = ev > 0.f ? ev : ALPHA * ev;
            p1 = (am.y > 0) ? __expf(ev - mi) : 0.f;
            ev = s1v + s2q.z; ev = ev > 0.f ? ev : ALPHA * ev;
            p2 = (am.z > 0) ? __expf(ev - mi) : 0.f;
            ev = s1v + s2q.w; ev = ev > 0.f ? ev : ALPHA * ev;
            p3 = (am.w > 0) ? __expf(ev - mi) : 0.f;
            zloc += (p0 + p1) + (p2 + p3);

            __nv_bfloat16 h0 = __float2bfloat16_rn(p0);
            __nv_bfloat16 h1 = __float2bfloat16_rn(p1);
            __nv_bfloat16 h2 = __float2bfloat16_rn(p2);
            __nv_bfloat16 h3 = __float2bfloat16_rn(p3);
            __nv_bfloat162 hA = __halves2bfloat162(h0, h1);
            __nv_bfloat162 hB = __halves2bfloat162(h2, h3);
            __nv_bfloat162 lA = __halves2bfloat162(
                __float2bfloat16_rn(p0 - __bfloat162float(h0)),
                __float2bfloat16_rn(p1 - __bfloat162float(h1)));
            __nv_bfloat162 lB = __halves2bfloat162(
                __float2bfloat16_rn(p2 - __bfloat162float(h2)),
                __float2bfloat16_rn(p3 - __bfloat162float(h3)));
            uint2 hv, lv;
            hv.x = *reinterpret_cast<uint32_t*>(&hA);
            hv.y = *reinterpret_cast<uint32_t*>(&hB);
            lv.x = *reinterpret_cast<uint32_t*>(&lA);
            lv.y = *reinterpret_cast<uint32_t*>(&lB);
            const uint32_t sa = r * VST + (jbase + g * 4) * 2;
            *(uint2*)(smem + SM_PH + sa) = hv;
            *(uint2*)(smem + SM_PL + sa) = lv;
        }
        __syncthreads();

        // ---- HMMA: acc += Ph*Vh + Ph*Vl + Pl*Vh ----
#pragma unroll
        for (int ks = 0; ks < 4; ks++) {
            const uint32_t kb = ks * 32 + ldr;   // byte offset of k pair
            uint32_t ah[2][4], al[2][4];
#pragma unroll
            for (int mt = 0; mt < 2; mt++) {
                const uint32_t base = (m0w + mt * 16 + ldq) * VST + kb;
                ah[mt][0] = *(const uint32_t*)(smem + SM_PH + base);
                ah[mt][1] = *(const uint32_t*)(smem + SM_PH + base + 8 * VST);
                ah[mt][2] = *(const uint32_t*)(smem + SM_PH + base + 16);
                ah[mt][3] = *(const uint32_t*)(smem + SM_PH + base + 8 * VST + 16);
                al[mt][0] = *(const uint32_t*)(smem + SM_PL + base);
                al[mt][1] = *(const uint32_t*)(smem + SM_PL + base + 8 * VST);
                al[mt][2] = *(const uint32_t*)(smem + SM_PL + base + 16);
                al[mt][3] = *(const uint32_t*)(smem + SM_PL + base + 8 * VST + 16);
            }
#pragma unroll
            for (int nt = 0; nt < 8; nt++) {
                const uint32_t bo = (n0w + nt * 8 + ldq) * VST + kb;
                uint32_t bh[2], bl[2];
                bh[0] = *(const uint32_t*)(smem + SM_VH + bo);
                bh[1] = *(const uint32_t*)(smem + SM_VH + bo + 16);
                bl[0] = *(const uint32_t*)(smem + SM_VL + bo);
                bl[1] = *(const uint32_t*)(smem + SM_VL + bo + 16);
#pragma unroll
                for (int mt = 0; mt < 2; mt++) {
                    mma16816(acc[mt][nt], ah[mt], bh);
                    mma16816(acc[mt][nt], ah[mt], bl);
                    mma16816(acc[mt][nt], al[mt], bh);
                }
            }
        }
        __syncthreads();
    }

    // ---- Z reduction (quads share a row) ----
    zloc += __shfl_xor_sync(0xffffffffu, zloc, 1);
    zloc += __shfl_xor_sync(0xffffffffu, zloc, 2);
    if ((tid & 3) == 0) *(float*)(smem + SM_ZS + r * 4) = zloc;
    __syncthreads();

    // ---- epilogue: out = acc / Z ----
    const float* Zs = (const float*)(smem + SM_ZS);
#pragma unroll
    for (int mt = 0; mt < 2; mt++) {
        const int row0 = m0w + mt * 16 + ldq;
        const float rz0 = 1.f / Zs[row0];
        const float rz1 = 1.f / Zs[row0 + 8];
        float* __restrict__ o0 = out + ((size_t)b * NN + i0 + row0) * FF;
        float* __restrict__ o1 = o0 + 8 * FF;
#pragma unroll
        for (int nt = 0; nt < 8; nt++) {
            const int col = n0w + nt * 8 + (lane & 3) * 2;
            float2 v0 = make_float2(acc[mt][nt][0] * rz0, acc[mt][nt][1] * rz0);
            float2 v1 = make_float2(acc[mt][nt][2] * rz1, acc[mt][nt][3] * rz1);
            *(float2*)&o0[col] = v0;
            *(float2*)&o1[col] = v1;
        }
    }
}

// ============================================================
// launch
// ============================================================
extern "C" void kernel_launch(void* const* d_in, const int* in_sizes, int n_in,
                              void* d_out, int out_size)
{
    const float* h   = (const float*)d_in[0];
    const int*   adj = (const int*)d_in[1];
    const float* W   = (const float*)d_in[2];
    const float* a   = (const float*)d_in[3];
    float* out = (float*)d_out;

    cudaFuncSetAttribute(attn_mma_kernel,
                         cudaFuncAttributeMaxDynamicSharedMemorySize, SM_TOTAL);

    dim3 g1(BB * NN / 64, FF / 64);
    gemm_wh_kernel<<<g1, 256>>>(h, W);

    s1s2_kernel<<<BB * NN / 8, 256>>>(a);
    s2max_kernel<<<BB, 256>>>();

    dim3 g3(NN / 32, FF / 32, BB);
    split_transpose_kernel<<<g3, 256>>>();

    dim3 g4(NN / TI, BB);
    attn_mma_kernel<<<g4, 256, SM_TOTAL>>>(adj, out);
}

// round 5
// speedup vs baseline: 4.6600x; 1.4347x over previous
#include <cuda_runtime.h>
#include <cuda_bf16.h>
#include <cuda_fp16.h>
#include <cstdint>

#define BB 8
#define NN 2048
#define FF 256
#define ALPHA 0.2f

// -------- scratch (device globals; no allocation allowed) --------
__device__ float g_Wh[BB * NN * FF];          // 16 MB
__device__ __half g_WhT_hi[BB * FF * NN];     // 8 MB  (Wh^T, fp16 high part)
__device__ __half g_WhT_lo[BB * FF * NN];     // 8 MB  (Wh^T, fp16 low part)
__device__ float g_s1[BB * NN];
__device__ float g_s2[BB * NN];
__device__ float g_s2max[BB];

// ============================================================
// Kernel 1: Wh = h @ W   (fp32 CUDA-core)
// ============================================================
__global__ __launch_bounds__(256) void gemm_wh_kernel(
    const float* __restrict__ h, const float* __restrict__ W)
{
    __shared__ float As[16][68];
    __shared__ float Bs[16][68];

    const int tid = threadIdx.x;
    const int tx = tid & 15;
    const int ty = tid >> 4;
    const int m0 = blockIdx.x * 64;
    const int n0 = blockIdx.y * 64;

    const int la_m  = tid >> 2;
    const int la_k4 = (tid & 3) * 4;
    const int lb_k  = tid >> 4;
    const int lb_n4 = (tid & 15) * 4;

    float acc[4][4];
#pragma unroll
    for (int i = 0; i < 4; i++)
#pragma unroll
        for (int j = 0; j < 4; j++) acc[i][j] = 0.f;

    for (int k0 = 0; k0 < FF; k0 += 16) {
        float4 av = *(const float4*)&h[(size_t)(m0 + la_m) * FF + k0 + la_k4];
        float4 bv = *(const float4*)&W[(size_t)(k0 + lb_k) * FF + n0 + lb_n4];
        As[la_k4 + 0][la_m] = av.x;
        As[la_k4 + 1][la_m] = av.y;
        As[la_k4 + 2][la_m] = av.z;
        As[la_k4 + 3][la_m] = av.w;
        *(float4*)&Bs[lb_k][lb_n4] = bv;
        __syncthreads();
#pragma unroll
        for (int k = 0; k < 16; k++) {
            float4 a4 = *(const float4*)&As[k][ty * 4];
            float4 b4 = *(const float4*)&Bs[k][tx * 4];
            float a[4] = {a4.x, a4.y, a4.z, a4.w};
            float b[4] = {b4.x, b4.y, b4.z, b4.w};
#pragma unroll
            for (int i = 0; i < 4; i++)
#pragma unroll
                for (int j = 0; j < 4; j++) acc[i][j] += a[i] * b[j];
        }
        __syncthreads();
    }
#pragma unroll
    for (int i = 0; i < 4; i++) {
        float4 v = make_float4(acc[i][0], acc[i][1], acc[i][2], acc[i][3]);
        *(float4*)&g_Wh[(size_t)(m0 + ty * 4 + i) * FF + n0 + tx * 4] = v;
    }
}

// ============================================================
// Kernel 2: s1/s2 row dots
// ============================================================
__global__ __launch_bounds__(256) void s1s2_kernel(const float* __restrict__ a)
{
    const int warp = threadIdx.x >> 5;
    const int lane = threadIdx.x & 31;
    const int row = blockIdx.x * 8 + warp;
    const float* wh = g_Wh + (size_t)row * FF;
    float s1 = 0.f, s2 = 0.f;
#pragma unroll
    for (int k = 0; k < 8; k++) {
        float w = wh[k * 32 + lane];
        s1 += w * a[k * 32 + lane];
        s2 += w * a[FF + k * 32 + lane];
    }
#pragma unroll
    for (int o = 16; o; o >>= 1) {
        s1 += __shfl_xor_sync(0xffffffffu, s1, o);
        s2 += __shfl_xor_sync(0xffffffffu, s2, o);
    }
    if (lane == 0) { g_s1[row] = s1; g_s2[row] = s2; }
}

// ============================================================
// Kernel 3: per-batch max of s2
// ============================================================
__global__ __launch_bounds__(256) void s2max_kernel()
{
    __shared__ float red[256];
    const int b = blockIdx.x;
    float m = -1e30f;
    for (int i = threadIdx.x; i < NN; i += 256) m = fmaxf(m, g_s2[b * NN + i]);
    red[threadIdx.x] = m;
    __syncthreads();
#pragma unroll
    for (int s = 128; s; s >>= 1) {
        if (threadIdx.x < s) red[threadIdx.x] = fmaxf(red[threadIdx.x], red[threadIdx.x + s]);
        __syncthreads();
    }
    if (threadIdx.x == 0) g_s2max[b] = red[0];
}

// ============================================================
// Kernel 3b: Wh -> Wh^T split to fp16 hi/lo (per batch transpose)
// ============================================================
__global__ __launch_bounds__(256) void split_transpose_kernel()
{
    __shared__ float t[32][33];
    const int b = blockIdx.z;
    const int n0 = blockIdx.x * 32, f0 = blockIdx.y * 32;
    const int x = threadIdx.x & 31, y = threadIdx.x >> 5;   // y 0..7
    const float* src = g_Wh + ((size_t)b * NN + n0) * FF + f0;
#pragma unroll
    for (int r = 0; r < 4; r++)
        t[y * 4 + r][x] = src[(size_t)(y * 4 + r) * FF + x];
    __syncthreads();
#pragma unroll
    for (int r = 0; r < 4; r++) {
        const int f = y * 4 + r;
        float v = t[x][f];
        __half hi = __float2half_rn(v);
        float rem = v - __half2float(hi);
        size_t o = ((size_t)b * FF + f0 + f) * NN + n0 + x;
        g_WhT_hi[o] = hi;
        g_WhT_lo[o] = __float2half_rn(rem);
    }
}

// ============================================================
// Kernel 4: fused masked softmax + PV via mma.sync fp16 2-pass
// CTA: 64 queries x 256 features, 8 warps (2m x 4n), warp 32q x 64f
// K-tile KJ=64 over j. 144B row stride => conflict-free LDSM.
// ============================================================
#define TI 64
#define KJ 64
#define VST 144

#define SM_VH 0
#define SM_VL (SM_VH + FF * VST)            // 36864
#define SM_PH (SM_VL + FF * VST)            // 73728
#define SM_ZS (SM_PH + TI * VST)            // 82944
#define SM_TOTAL (SM_ZS + TI * 4)           // 83200

__device__ __forceinline__ void mma16816(float* c, const uint32_t* a, const uint32_t* b)
{
    asm volatile(
        "mma.sync.aligned.m16n8k16.row.col.f32.f16.f16.f32 "
        "{%0,%1,%2,%3}, {%4,%5,%6,%7}, {%8,%9}, {%0,%1,%2,%3};"
        : "+f"(c[0]), "+f"(c[1]), "+f"(c[2]), "+f"(c[3])
        : "r"(a[0]), "r"(a[1]), "r"(a[2]), "r"(a[3]), "r"(b[0]), "r"(b[1]));
}

__device__ __forceinline__ void ldsm_x4(uint32_t* r, uint32_t addr)
{
    asm volatile("ldmatrix.sync.aligned.m8n8.x4.shared.b16 {%0,%1,%2,%3}, [%4];"
        : "=r"(r[0]), "=r"(r[1]), "=r"(r[2]), "=r"(r[3]) : "r"(addr));
}

__device__ __forceinline__ uint32_t smem_u32(const void* p) {
    uint32_t a;
    asm("{ .reg .u64 t; cvta.to.shared.u64 t, %1; cvt.u32.u64 %0, t; }" : "=r"(a) : "l"(p));
    return a;
}

__global__ __launch_bounds__(256, 2) void attn_mma_kernel(
    const int* __restrict__ adj, float* __restrict__ out)
{
    extern __shared__ char smem[];
    const uint32_t smem_base = smem_u32(smem);
    const int tid = threadIdx.x;
    const int wid = tid >> 5;
    const int lane = tid & 31;
    const int b = blockIdx.y;
    const int i0 = blockIdx.x * TI;

    // warp tile: rows m0w..+31, cols n0w..+63
    const int m0w = (wid & 1) * 32;
    const int n0w = (wid >> 1) * 64;

    // P-compute mapping: thread -> (row r, 16 j's at jbase)
    const int r = tid >> 2;
    const int jbase = (tid & 3) * 16;

    const float s1v = g_s1[b * NN + i0 + r];
    const float ms2 = g_s2max[b];
    const float tpre = s1v + ms2;
    const float mi = tpre > 0.f ? tpre : ALPHA * tpre;
    float zloc = 0.f;

    const int* __restrict__ adjR = adj + ((size_t)b * NN + i0 + r) * NN;
    const float* __restrict__ s2B = g_s2 + b * NN;
    const uint4* __restrict__ whtHi = (const uint4*)(g_WhT_hi + (size_t)b * FF * NN);
    const uint4* __restrict__ whtLo = (const uint4*)(g_WhT_lo + (size_t)b * FF * NN);

    float acc[2][8][4];
#pragma unroll
    for (int mt = 0; mt < 2; mt++)
#pragma unroll
        for (int nt = 0; nt < 8; nt++)
#pragma unroll
            for (int q = 0; q < 4; q++) acc[mt][nt][q] = 0.f;

    // ldmatrix per-lane base offsets
    // A (P): g0: rows 0-7 k-low, g1: rows 8-15 k-low, g2: rows 0-7 k-hi, g3: rows 8-15 k-hi
    const uint32_t a_off = smem_base + SM_PH
        + (uint32_t)(m0w + ((lane >> 3) & 1) * 8 + (lane & 7)) * VST
        + (uint32_t)(lane >> 4) * 16;
    // B (V^T): g0: n rows 0-7 k-low, g1: rows 0-7 k-hi, g2: rows 8-15 k-low, g3: rows 8-15 k-hi
    const uint32_t b_row = (uint32_t)(n0w + ((lane >> 4) & 1) * 8 + (lane & 7)) * VST
        + (uint32_t)((lane >> 3) & 1) * 16;

    for (int jt = 0; jt < NN / KJ; jt++) {
        const int j0 = jt * KJ;

        // ---- stage V^T hi/lo tiles: 256 f-rows x 64 j fp16 ----
#pragma unroll
        for (int it = 0; it < 8; it++) {
            const int idx = tid + it * 256;
            const int f = idx >> 3;
            const int c = idx & 7;
            const int gi = f * (NN / 8) + (j0 >> 3) + c;
            const uint32_t so = f * VST + c * 16;
            *(uint4*)(smem + SM_VH + so) = whtHi[gi];
            *(uint4*)(smem + SM_VL + so) = whtLo[gi];
        }

        // ---- compute P tile [64 x 64] fp16 ----
#pragma unroll
        for (int g = 0; g < 4; g++) {
            const int j = j0 + jbase + g * 4;
            int4 am = *(const int4*)&adjR[j];
            float4 s2q = *(const float4*)&s2B[j];
            float p0, p1, p2, p3, ev;
            ev = s1v + s2q.x; ev = ev > 0.f ? ev : ALPHA * ev;
            p0 = (am.x > 0) ? __expf(ev - mi) : 0.f;
            ev = s1v + s2q.y; ev = ev > 0.f ? ev : ALPHA * ev;
            p1 = (am.y > 0) ? __expf(ev - mi) : 0.f;
            ev = s1v + s2q.z; ev = ev > 0.f ? ev : ALPHA * ev;
            p2 = (am.z > 0) ? __expf(ev - mi) : 0.f;
            ev = s1v + s2q.w; ev = ev > 0.f ? ev : ALPHA * ev;
            p3 = (am.w > 0) ? __expf(ev - mi) : 0.f;
            zloc += (p0 + p1) + (p2 + p3);

            __half2 hA = __floats2half2_rn(p0, p1);
            __half2 hB = __floats2half2_rn(p2, p3);
            uint2 hv;
            hv.x = *reinterpret_cast<uint32_t*>(&hA);
            hv.y = *reinterpret_cast<uint32_t*>(&hB);
            *(uint2*)(smem + SM_PH + r * VST + (jbase + g * 4) * 2) = hv;
        }
        __syncthreads();

        // ---- HMMA: acc += P*Vh + P*Vl ----
#pragma unroll
        for (int ks = 0; ks < 4; ks++) {
            const uint32_t kb = ks * 32;
            uint32_t ah[2][4];
            ldsm_x4(ah[0], a_off + kb);
            ldsm_x4(ah[1], a_off + 16 * VST + kb);
#pragma unroll
            for (int ntp = 0; ntp < 4; ntp++) {
                const uint32_t bo = b_row + ntp * 16 * VST + kb;
                uint32_t bh[4], bl[4];
                ldsm_x4(bh, smem_base + SM_VH + bo);
                ldsm_x4(bl, smem_base + SM_VL + bo);
#pragma unroll
                for (int mt = 0; mt < 2; mt++) {
                    mma16816(acc[mt][ntp * 2 + 0], ah[mt], &bh[0]);
                    mma16816(acc[mt][ntp * 2 + 1], ah[mt], &bh[2]);
                    mma16816(acc[mt][ntp * 2 + 0], ah[mt], &bl[0]);
                    mma16816(acc[mt][ntp * 2 + 1], ah[mt], &bl[2]);
                }
            }
        }
        __syncthreads();
    }

    // ---- Z reduction (quads share a row) ----
    zloc += __shfl_xor_sync(0xffffffffu, zloc, 1);
    zloc += __shfl_xor_sync(0xffffffffu, zloc, 2);
    if ((tid & 3) == 0) *(float*)(smem + SM_ZS + r * 4) = zloc;
    __syncthreads();

    // ---- epilogue: out = acc / Z ----
    const float* Zs = (const float*)(smem + SM_ZS);
    const int ldq = lane >> 2;
#pragma unroll
    for (int mt = 0; mt < 2; mt++) {
        const int row0 = m0w + mt * 16 + ldq;
        const float rz0 = 1.f / Zs[row0];
        const float rz1 = 1.f / Zs[row0 + 8];
        float* __restrict__ o0 = out + ((size_t)b * NN + i0 + row0) * FF;
        float* __restrict__ o1 = o0 + 8 * FF;
#pragma unroll
        for (int nt = 0; nt < 8; nt++) {
            const int col = n0w + nt * 8 + (lane & 3) * 2;
            float2 v0 = make_float2(acc[mt][nt][0] * rz0, acc[mt][nt][1] * rz0);
            float2 v1 = make_float2(acc[mt][nt][2] * rz1, acc[mt][nt][3] * rz1);
            *(float2*)&o0[col] = v0;
            *(float2*)&o1[col] = v1;
        }
    }
}

// ============================================================
// launch
// ============================================================
extern "C" void kernel_launch(void* const* d_in, const int* in_sizes, int n_in,
                              void* d_out, int out_size)
{
    const float* h   = (const float*)d_in[0];
    const int*   adj = (const int*)d_in[1];
    const float* W   = (const float*)d_in[2];
    const float* a   = (const float*)d_in[3];
    float* out = (float*)d_out;

    cudaFuncSetAttribute(attn_mma_kernel,
                         cudaFuncAttributeMaxDynamicSharedMemorySize, SM_TOTAL);

    dim3 g1(BB * NN / 64, FF / 64);
    gemm_wh_kernel<<<g1, 256>>>(h, W);

    s1s2_kernel<<<BB * NN / 8, 256>>>(a);
    s2max_kernel<<<BB, 256>>>();

    dim3 g3(NN / 32, FF / 32, BB);
    split_transpose_kernel<<<g3, 256>>>();

    dim3 g4(NN / TI, BB);
    attn_mma_kernel<<<g4, 256, SM_TOTAL>>>(adj, out);
}

// round 6
// speedup vs baseline: 7.1876x; 1.5424x over previous
#include <cuda_runtime.h>
#include <cuda_fp16.h>
#include <cstdint>

#define BB 8
#define NN 2048
#define FF 256
#define ALPHA 0.2f

// -------- scratch (device globals; no allocation allowed) --------
__device__ __half g_WhT_hi[BB * FF * NN];     // 8 MB  (Wh^T, fp16 high part)
__device__ __half g_WhT_lo[BB * FF * NN];     // 8 MB  (Wh^T, fp16 low part)
__device__ __half g_WT_hi[FF * FF];           // W^T fp16 hi  [f][k]
__device__ __half g_WT_lo[FF * FF];           // W^T fp16 lo
__device__ float g_s1[BB * NN];
__device__ float g_s2[BB * NN];
__device__ float g_s2max[BB];

// ============================================================
// common helpers
// ============================================================
__device__ __forceinline__ void mma16816(float* c, const uint32_t* a, const uint32_t* b)
{
    asm volatile(
        "mma.sync.aligned.m16n8k16.row.col.f32.f16.f16.f32 "
        "{%0,%1,%2,%3}, {%4,%5,%6,%7}, {%8,%9}, {%0,%1,%2,%3};"
        : "+f"(c[0]), "+f"(c[1]), "+f"(c[2]), "+f"(c[3])
        : "r"(a[0]), "r"(a[1]), "r"(a[2]), "r"(a[3]), "r"(b[0]), "r"(b[1]));
}
__device__ __forceinline__ void ldsm_x4(uint32_t* r, uint32_t addr)
{
    asm volatile("ldmatrix.sync.aligned.m8n8.x4.shared.b16 {%0,%1,%2,%3}, [%4];"
        : "=r"(r[0]), "=r"(r[1]), "=r"(r[2]), "=r"(r[3]) : "r"(addr));
}
__device__ __forceinline__ uint32_t smem_u32(const void* p) {
    uint32_t a;
    asm("{ .reg .u64 t; cvta.to.shared.u64 t, %1; cvt.u32.u64 %0, t; }" : "=r"(a) : "l"(p));
    return a;
}
#define CP_ASYNC16(dst, src) asm volatile("cp.async.cg.shared.global [%0], [%1], 16;" :: "r"(dst), "l"(src) : "memory")
#define CP_COMMIT()  asm volatile("cp.async.commit_group;" ::: "memory")
#define CP_WAIT0()   asm volatile("cp.async.wait_group 0;" ::: "memory")

#define VST 144   // smem row stride (64 fp16 + pad) -> conflict-free LDSM

// ============================================================
// Kernel 0: W [k][f] fp32 -> W^T hi/lo fp16 [f][k]
// ============================================================
__global__ __launch_bounds__(256) void prep_wt_kernel(const float* __restrict__ W)
{
    __shared__ float t[32][33];
    const int k0 = blockIdx.x * 32, f0 = blockIdx.y * 32;
    const int x = threadIdx.x & 31, y = threadIdx.x >> 5;
#pragma unroll
    for (int r = 0; r < 4; r++)
        t[y * 4 + r][x] = W[(size_t)(k0 + y * 4 + r) * FF + f0 + x];
    __syncthreads();
#pragma unroll
    for (int r = 0; r < 4; r++) {
        const int f = f0 + y * 4 + r;
        float v = t[x][y * 4 + r];
        __half hi = __float2half_rn(v);
        g_WT_hi[(size_t)f * FF + k0 + x] = hi;
        g_WT_lo[(size_t)f * FF + k0 + x] = __float2half_rn(v - __half2float(hi));
    }
}

// ============================================================
// Kernel 1: fused Wh GEMM (split-fp16 3-pass mma) + s1/s2 + WhT hi/lo
// CTA: 64 nodes x 256 features, 8 warps (2m x 4n)
// ============================================================
#define GS_BH 0
#define GS_BL (GS_BH + FF * VST)            // 36864
#define GS_AH (GS_BL + FF * VST)            // 73728
#define GS_AL (GS_AH + 64 * VST)            // 82944
#define GS_S1P (GS_AL + 64 * VST)           // 92160
#define GS_S2P (GS_S1P + 64 * 4)            // 92416
#define GS_TOTAL (GS_S2P + 64 * 4)          // 92672
// epilogue transpose staging reuses [0, 67584) (BH/BL dead by then)
#define TSTR 66

__global__ __launch_bounds__(256, 2) void gemm_fused_kernel(
    const float* __restrict__ h, const float* __restrict__ aVec)
{
    extern __shared__ char smem[];
    const uint32_t smem_base = smem_u32(smem);
    const int tid = threadIdx.x;
    const int wid = tid >> 5;
    const int lane = tid & 31;
    const int m0 = blockIdx.x * 64;            // global node row (0..16383)
    const int b = m0 / NN;
    const int n_in_b = m0 - b * NN;

    const int m0w = (wid & 1) * 32;
    const int n0w = (wid >> 1) * 64;

    float acc[2][8][4];
#pragma unroll
    for (int mt = 0; mt < 2; mt++)
#pragma unroll
        for (int nt = 0; nt < 8; nt++)
#pragma unroll
            for (int q = 0; q < 4; q++) acc[mt][nt][q] = 0.f;

    const uint32_t a_off_h = smem_base + GS_AH
        + (uint32_t)(m0w + ((lane >> 3) & 1) * 8 + (lane & 7)) * VST
        + (uint32_t)(lane >> 4) * 16;
    const uint32_t a_off_l = a_off_h + (GS_AL - GS_AH);
    const uint32_t b_row = (uint32_t)(n0w + ((lane >> 4) & 1) * 8 + (lane & 7)) * VST
        + (uint32_t)((lane >> 3) & 1) * 16;

    for (int kt = 0; kt < 4; kt++) {
        const int k0 = kt * 64;
        // ---- B: W^T hi/lo tiles via cp.async (256 f-rows x 64 k) ----
#pragma unroll
        for (int it = 0; it < 8; it++) {
            const int idx = tid + it * 256;
            const int f = idx >> 3;
            const int c = idx & 7;
            const uint32_t so = f * VST + c * 16;
            const size_t go = (size_t)f * FF + k0 + c * 8;
            CP_ASYNC16(smem_base + GS_BH + so, (const char*)(g_WT_hi + go));
            CP_ASYNC16(smem_base + GS_BL + so, (const char*)(g_WT_lo + go));
        }
        CP_COMMIT();
        // ---- A: h tile fp32 -> hi/lo fp16 ----
#pragma unroll
        for (int t = 0; t < 4; t++) {
            const int idx = tid + t * 256;         // float4 index
            const int row = idx >> 4;
            const int cg = (idx & 15) * 4;
            float4 v = *(const float4*)&h[(size_t)(m0 + row) * FF + k0 + cg];
            __half hx = __float2half_rn(v.x), hy = __float2half_rn(v.y);
            __half hz = __float2half_rn(v.z), hw = __float2half_rn(v.w);
            __half2 hA = __halves2half2(hx, hy), hB = __halves2half2(hz, hw);
            __half2 lA = __halves2half2(__float2half_rn(v.x - __half2float(hx)),
                                        __float2half_rn(v.y - __half2float(hy)));
            __half2 lB = __halves2half2(__float2half_rn(v.z - __half2float(hz)),
                                        __float2half_rn(v.w - __half2float(hw)));
            uint2 hv, lv;
            hv.x = *reinterpret_cast<uint32_t*>(&hA);
            hv.y = *reinterpret_cast<uint32_t*>(&hB);
            lv.x = *reinterpret_cast<uint32_t*>(&lA);
            lv.y = *reinterpret_cast<uint32_t*>(&lB);
            *(uint2*)(smem + GS_AH + row * VST + cg * 2) = hv;
            *(uint2*)(smem + GS_AL + row * VST + cg * 2) = lv;
        }
        CP_WAIT0();
        __syncthreads();

        // ---- MMA: acc += Ah*Bh + Ah*Bl + Al*Bh ----
#pragma unroll
        for (int ks = 0; ks < 4; ks++) {
            const uint32_t kb = ks * 32;
            uint32_t ah[2][4], al[2][4];
            ldsm_x4(ah[0], a_off_h + kb);
            ldsm_x4(ah[1], a_off_h + 16 * VST + kb);
            ldsm_x4(al[0], a_off_l + kb);
            ldsm_x4(al[1], a_off_l + 16 * VST + kb);
#pragma unroll
            for (int ntp = 0; ntp < 4; ntp++) {
                const uint32_t bo = b_row + ntp * 16 * VST + kb;
                uint32_t bh[4], bl[4];
                ldsm_x4(bh, smem_base + GS_BH + bo);
                ldsm_x4(bl, smem_base + GS_BL + bo);
#pragma unroll
                for (int mt = 0; mt < 2; mt++) {
                    mma16816(acc[mt][ntp * 2 + 0], ah[mt], &bh[0]);
                    mma16816(acc[mt][ntp * 2 + 1], ah[mt], &bh[2]);
                    mma16816(acc[mt][ntp * 2 + 0], ah[mt], &bl[0]);
                    mma16816(acc[mt][ntp * 2 + 1], ah[mt], &bl[2]);
                    mma16816(acc[mt][ntp * 2 + 0], al[mt], &bh[0]);
                    mma16816(acc[mt][ntp * 2 + 1], al[mt], &bh[2]);
                }
            }
        }
        __syncthreads();
    }

    // ================= epilogue =================
    const int ldq = lane >> 2;
    float* st = (float*)smem;                 // transpose staging [256 f][TSTR]
    float* s1p = (float*)(smem + GS_S1P);
    float* s2p = (float*)(smem + GS_S2P);

    // phase 1: stage acc transposed + zero partials
    if (tid < 64) { s1p[tid] = 0.f; s2p[tid] = 0.f; }
#pragma unroll
    for (int mt = 0; mt < 2; mt++) {
        const int r0 = m0w + mt * 16 + ldq;
#pragma unroll
        for (int nt = 0; nt < 8; nt++) {
            const int c0 = n0w + nt * 8 + (lane & 3) * 2;
            st[(c0 + 0) * TSTR + r0] = acc[mt][nt][0];
            st[(c0 + 1) * TSTR + r0] = acc[mt][nt][1];
            st[(c0 + 0) * TSTR + r0 + 8] = acc[mt][nt][2];
            st[(c0 + 1) * TSTR + r0 + 8] = acc[mt][nt][3];
        }
    }
    __syncthreads();

    // phase 2: s1/s2 partial dots (per-lane over its 16 cols), quad reduce, atomicAdd
#pragma unroll
    for (int mt = 0; mt < 2; mt++) {
        const int r0 = m0w + mt * 16 + ldq;
        float s1x = 0.f, s1y = 0.f, s2x = 0.f, s2y = 0.f;
#pragma unroll
        for (int nt = 0; nt < 8; nt++) {
            const int c0 = n0w + nt * 8 + (lane & 3) * 2;
            float a10 = aVec[c0], a11 = aVec[c0 + 1];
            float a20 = aVec[FF + c0], a21 = aVec[FF + c0 + 1];
            s1x += acc[mt][nt][0] * a10 + acc[mt][nt][1] * a11;
            s1y += acc[mt][nt][2] * a10 + acc[mt][nt][3] * a11;
            s2x += acc[mt][nt][0] * a20 + acc[mt][nt][1] * a21;
            s2y += acc[mt][nt][2] * a20 + acc[mt][nt][3] * a21;
        }
#pragma unroll
        for (int o = 1; o <= 2; o <<= 1) {
            s1x += __shfl_xor_sync(0xffffffffu, s1x, o);
            s1y += __shfl_xor_sync(0xffffffffu, s1y, o);
            s2x += __shfl_xor_sync(0xffffffffu, s2x, o);
            s2y += __shfl_xor_sync(0xffffffffu, s2y, o);
        }
        if ((lane & 3) == 0) {
            atomicAdd(&s1p[r0], s1x);
            atomicAdd(&s1p[r0 + 8], s1y);
            atomicAdd(&s2p[r0], s2x);
            atomicAdd(&s2p[r0 + 8], s2y);
        }
    }
    __syncthreads();

    // phase 3: store WhT hi/lo + s1/s2
    __half* whtHiB = g_WhT_hi + (size_t)b * FF * NN + n_in_b;
    __half* whtLoB = g_WhT_lo + (size_t)b * FF * NN + n_in_b;
#pragma unroll
    for (int t = 0; t < 16; t++) {
        const int idx = tid + t * 256;     // (f, m4) group
        const int f = idx >> 4;
        const int m4 = (idx & 15) * 4;
        float v0 = st[f * TSTR + m4 + 0];
        float v1 = st[f * TSTR + m4 + 1];
        float v2 = st[f * TSTR + m4 + 2];
        float v3 = st[f * TSTR + m4 + 3];
        __half h0 = __float2half_rn(v0), h1 = __float2half_rn(v1);
        __half h2 = __float2half_rn(v2), h3 = __float2half_rn(v3);
        __half2 hA = __halves2half2(h0, h1), hB = __halves2half2(h2, h3);
        __half2 lA = __halves2half2(__float2half_rn(v0 - __half2float(h0)),
                                    __float2half_rn(v1 - __half2float(h1)));
        __half2 lB = __halves2half2(__float2half_rn(v2 - __half2float(h2)),
                                    __float2half_rn(v3 - __half2float(h3)));
        uint2 hv, lv;
        hv.x = *reinterpret_cast<uint32_t*>(&hA);
        hv.y = *reinterpret_cast<uint32_t*>(&hB);
        lv.x = *reinterpret_cast<uint32_t*>(&lA);
        lv.y = *reinterpret_cast<uint32_t*>(&lB);
        *(uint2*)(whtHiB + (size_t)f * NN + m4) = hv;
        *(uint2*)(whtLoB + (size_t)f * NN + m4) = lv;
    }
    if (tid < 64) {
        g_s1[m0 + tid] = s1p[tid];
        g_s2[m0 + tid] = s2p[tid];
    }
}

// ============================================================
// Kernel 2: per-batch max of s2
// ============================================================
__global__ __launch_bounds__(256) void s2max_kernel()
{
    __shared__ float red[256];
    const int b = blockIdx.x;
    float m = -1e30f;
    for (int i = threadIdx.x; i < NN; i += 256) m = fmaxf(m, g_s2[b * NN + i]);
    red[threadIdx.x] = m;
    __syncthreads();
#pragma unroll
    for (int s = 128; s; s >>= 1) {
        if (threadIdx.x < s) red[threadIdx.x] = fmaxf(red[threadIdx.x], red[threadIdx.x + s]);
        __syncthreads();
    }
    if (threadIdx.x == 0) g_s2max[b] = red[0];
}

// ============================================================
// Kernel 3: fused masked softmax + PV via mma.sync fp16 2-pass
// cp.async V staging + adj register prefetch
// ============================================================
#define TI 64
#define KJ 64
#define NJ (NN / KJ)

#define SM_VH 0
#define SM_VL (SM_VH + FF * VST)            // 36864
#define SM_PH (SM_VL + FF * VST)            // 73728
#define SM_ZS (SM_PH + TI * VST)            // 82944
#define SM_TOTAL (SM_ZS + TI * 4)           // 83200

__global__ __launch_bounds__(256, 2) void attn_mma_kernel(
    const int* __restrict__ adj, float* __restrict__ out)
{
    extern __shared__ char smem[];
    const uint32_t smem_base = smem_u32(smem);
    const int tid = threadIdx.x;
    const int wid = tid >> 5;
    const int lane = tid & 31;
    const int b = blockIdx.y;
    const int i0 = blockIdx.x * TI;

    const int m0w = (wid & 1) * 32;
    const int n0w = (wid >> 1) * 64;

    const int r = tid >> 2;
    const int jbase = (tid & 3) * 16;

    const float s1v = g_s1[b * NN + i0 + r];
    const float ms2 = g_s2max[b];
    const float tpre = s1v + ms2;
    const float mi = tpre > 0.f ? tpre : ALPHA * tpre;
    float zloc = 0.f;

    const int* __restrict__ adjR = adj + ((size_t)b * NN + i0 + r) * NN;
    const float* __restrict__ s2B = g_s2 + b * NN;
    const __half* __restrict__ whtHi = g_WhT_hi + (size_t)b * FF * NN;
    const __half* __restrict__ whtLo = g_WhT_lo + (size_t)b * FF * NN;

    float acc[2][8][4];
#pragma unroll
    for (int mt = 0; mt < 2; mt++)
#pragma unroll
        for (int nt = 0; nt < 8; nt++)
#pragma unroll
            for (int q = 0; q < 4; q++) acc[mt][nt][q] = 0.f;

    const uint32_t a_off = smem_base + SM_PH
        + (uint32_t)(m0w + ((lane >> 3) & 1) * 8 + (lane & 7)) * VST
        + (uint32_t)(lane >> 4) * 16;
    const uint32_t b_row = (uint32_t)(n0w + ((lane >> 4) & 1) * 8 + (lane & 7)) * VST
        + (uint32_t)((lane >> 3) & 1) * 16;

    // prefetch adj for tile 0
    int4 am_pf[4];
#pragma unroll
    for (int g = 0; g < 4; g++)
        am_pf[g] = *(const int4*)&adjR[jbase + g * 4];

    for (int jt = 0; jt < NJ; jt++) {
        const int j0 = jt * KJ;

        // ---- V^T hi/lo tiles via cp.async ----
#pragma unroll
        for (int it = 0; it < 8; it++) {
            const int idx = tid + it * 256;
            const int f = idx >> 3;
            const int c = idx & 7;
            const uint32_t so = f * VST + c * 16;
            const size_t go = (size_t)f * NN + j0 + c * 8;
            CP_ASYNC16(smem_base + SM_VH + so, (const char*)(whtHi + go));
            CP_ASYNC16(smem_base + SM_VL + so, (const char*)(whtLo + go));
        }
        CP_COMMIT();

        // ---- compute P tile [64 x 64] fp16 from prefetched adj ----
#pragma unroll
        for (int g = 0; g < 4; g++) {
            const int j = j0 + jbase + g * 4;
            int4 am = am_pf[g];
            float4 s2q = *(const float4*)&s2B[j];
            float p0, p1, p2, p3, ev;
            ev = s1v + s2q.x; ev = ev > 0.f ? ev : ALPHA * ev;
            p0 = (am.x > 0) ? __expf(ev - mi) : 0.f;
            ev = s1v + s2q.y; ev = ev > 0.f ? ev : ALPHA * ev;
            p1 = (am.y > 0) ? __expf(ev - mi) : 0.f;
            ev = s1v + s2q.z; ev = ev > 0.f ? ev : ALPHA * ev;
            p2 = (am.z > 0) ? __expf(ev - mi) : 0.f;
            ev = s1v + s2q.w; ev = ev > 0.f ? ev : ALPHA * ev;
            p3 = (am.w > 0) ? __expf(ev - mi) : 0.f;
            zloc += (p0 + p1) + (p2 + p3);

            __half2 hA = __floats2half2_rn(p0, p1);
            __half2 hB = __floats2half2_rn(p2, p3);
            uint2 hv;
            hv.x = *reinterpret_cast<uint32_t*>(&hA);
            hv.y = *reinterpret_cast<uint32_t*>(&hB);
            *(uint2*)(smem + SM_PH + r * VST + (jbase + g * 4) * 2) = hv;
        }

        // ---- prefetch adj for next tile (latency spans MMA phase) ----
        const int jn = (jt + 1 < NJ) ? j0 + KJ : j0;
#pragma unroll
        for (int g = 0; g < 4; g++)
            am_pf[g] = *(const int4*)&adjR[jn + jbase + g * 4];

        CP_WAIT0();
        __syncthreads();

        // ---- HMMA: acc += P*Vh + P*Vl ----
#pragma unroll
        for (int ks = 0; ks < 4; ks++) {
            const uint32_t kb = ks * 32;
            uint32_t ah[2][4];
            ldsm_x4(ah[0], a_off + kb);
            ldsm_x4(ah[1], a_off + 16 * VST + kb);
#pragma unroll
            for (int ntp = 0; ntp < 4; ntp++) {
                const uint32_t bo = b_row + ntp * 16 * VST + kb;
                uint32_t bh[4], bl[4];
                ldsm_x4(bh, smem_base + SM_VH + bo);
                ldsm_x4(bl, smem_base + SM_VL + bo);
#pragma unroll
                for (int mt = 0; mt < 2; mt++) {
                    mma16816(acc[mt][ntp * 2 + 0], ah[mt], &bh[0]);
                    mma16816(acc[mt][ntp * 2 + 1], ah[mt], &bh[2]);
                    mma16816(acc[mt][ntp * 2 + 0], ah[mt], &bl[0]);
                    mma16816(acc[mt][ntp * 2 + 1], ah[mt], &bl[2]);
                }
            }
        }
        __syncthreads();
    }

    // ---- Z reduction (quads share a row) ----
    zloc += __shfl_xor_sync(0xffffffffu, zloc, 1);
    zloc += __shfl_xor_sync(0xffffffffu, zloc, 2);
    if ((tid & 3) == 0) *(float*)(smem + SM_ZS + r * 4) = zloc;
    __syncthreads();

    // ---- epilogue: out = acc / Z ----
    const float* Zs = (const float*)(smem + SM_ZS);
    const int ldq = lane >> 2;
#pragma unroll
    for (int mt = 0; mt < 2; mt++) {
        const int row0 = m0w + mt * 16 + ldq;
        const float rz0 = 1.f / Zs[row0];
        const float rz1 = 1.f / Zs[row0 + 8];
        float* __restrict__ o0 = out + ((size_t)b * NN + i0 + row0) * FF;
        float* __restrict__ o1 = o0 + 8 * FF;
#pragma unroll
        for (int nt = 0; nt < 8; nt++) {
            const int col = n0w + nt * 8 + (lane & 3) * 2;
            float2 v0 = make_float2(acc[mt][nt][0] * rz0, acc[mt][nt][1] * rz0);
            float2 v1 = make_float2(acc[mt][nt][2] * rz1, acc[mt][nt][3] * rz1);
            *(float2*)&o0[col] = v0;
            *(float2*)&o1[col] = v1;
        }
    }
}

// ============================================================
// launch
// ============================================================
extern "C" void kernel_launch(void* const* d_in, const int* in_sizes, int n_in,
                              void* d_out, int out_size)
{
    const float* h   = (const float*)d_in[0];
    const int*   adj = (const int*)d_in[1];
    const float* W   = (const float*)d_in[2];
    const float* a   = (const float*)d_in[3];
    float* out = (float*)d_out;

    cudaFuncSetAttribute(gemm_fused_kernel,
                         cudaFuncAttributeMaxDynamicSharedMemorySize, GS_TOTAL);
    cudaFuncSetAttribute(attn_mma_kernel,
                         cudaFuncAttributeMaxDynamicSharedMemorySize, SM_TOTAL);

    dim3 g0(FF / 32, FF / 32);
    prep_wt_kernel<<<g0, 256>>>(W);

    gemm_fused_kernel<<<BB * NN / 64, 256, GS_TOTAL>>>(h, a);

    s2max_kernel<<<BB, 256>>>();

    dim3 g4(NN / TI, BB);
    attn_mma_kernel<<<g4, 256, SM_TOTAL>>>(adj, out);
}